// round 2
// baseline (speedup 1.0000x reference)
#include <cuda_runtime.h>

#define S_LEN 1024
#define DM 256
#define NH 8
#define DU 32
#define NT 16               // S_LEN / 64
#define TEMPC 0.078125f     // TEMP / (2*DU) = 5/64

// ---------------- scratch (no allocations allowed) ----------------
__device__ float g_Q[S_LEN * DM];
__device__ float g_K[S_LEN * DM];
__device__ float g_V[S_LEN * DM];
__device__ float g_O[S_LEN * DM];
__device__ float g_sumK[NH * S_LEN];
__device__ float g_pnum[NT * NH * S_LEN * DU];   // [jt][h][i][d]
__device__ float g_pden[NT * NH * S_LEN];        // [jt][h][i]

// ---------------- 64x64-tile fp32 GEMM body ----------------
// C[row, col] = act( A[S_LEN, DM] @ W[DM, DM] + b )
__device__ __forceinline__ void gemm_body(const float* __restrict__ A,
                                          const float* __restrict__ W,
                                          const float* __restrict__ b,
                                          float* __restrict__ C,
                                          bool sig, int bm, int bn)
{
    __shared__ float Ast[32][64];   // A tile, transposed: [k][m]
    __shared__ float Ws[32][64];    // W tile: [k][n]

    const int tid = threadIdx.x;
    const int tx = tid & 15;        // 0..15 -> 4 output cols
    const int ty = tid >> 4;        // 0..15 -> 4 output rows

    float c[4][4];
#pragma unroll
    for (int m = 0; m < 4; m++)
#pragma unroll
        for (int n = 0; n < 4; n++) c[m][n] = 0.f;

    for (int k0 = 0; k0 < DM; k0 += 32) {
        // load A tile (64 rows x 32 k) transposed into smem
#pragma unroll
        for (int l = 0; l < 2; l++) {
            int f = tid + l * 256;
            int m = f >> 3;
            int kc = (f & 7) << 2;
            float4 v = *(const float4*)&A[(bm * 64 + m) * DM + k0 + kc];
            Ast[kc + 0][m] = v.x;
            Ast[kc + 1][m] = v.y;
            Ast[kc + 2][m] = v.z;
            Ast[kc + 3][m] = v.w;
        }
        // load W tile (32 k x 64 n)
#pragma unroll
        for (int l = 0; l < 2; l++) {
            int f = tid + l * 256;
            int k = f >> 4;
            int nc = (f & 15) << 2;
            *(float4*)&Ws[k][nc] = *(const float4*)&W[(k0 + k) * DM + bn * 64 + nc];
        }
        __syncthreads();
#pragma unroll
        for (int k = 0; k < 32; k++) {
            float4 av = *(const float4*)&Ast[k][ty * 4];
            float4 wv = *(const float4*)&Ws[k][tx * 4];
            float am[4] = {av.x, av.y, av.z, av.w};
            float wn[4] = {wv.x, wv.y, wv.z, wv.w};
#pragma unroll
            for (int m = 0; m < 4; m++)
#pragma unroll
                for (int n = 0; n < 4; n++) c[m][n] += am[m] * wn[n];
        }
        __syncthreads();
    }

    // epilogue: bias (+ sigmoid), vectorized store
#pragma unroll
    for (int m = 0; m < 4; m++) {
        int row = bm * 64 + ty * 4 + m;
        float v[4];
#pragma unroll
        for (int n = 0; n < 4; n++) {
            float t = c[m][n] + b[bn * 64 + tx * 4 + n];
            if (sig) t = 1.0f / (1.0f + __expf(-t));
            v[n] = t;
        }
        float4 o;
        o.x = v[0]; o.y = v[1]; o.z = v[2]; o.w = v[3];
        *(float4*)&C[row * DM + bn * 64 + tx * 4] = o;
    }
}

__global__ __launch_bounds__(256) void qkv_kernel(const float* __restrict__ x,
                                                  const float* __restrict__ Wq, const float* __restrict__ bq,
                                                  const float* __restrict__ Wk, const float* __restrict__ bk,
                                                  const float* __restrict__ Wv, const float* __restrict__ bv)
{
    int z = blockIdx.z;
    const float* W = (z == 0) ? Wq : ((z == 1) ? Wk : Wv);
    const float* b = (z == 0) ? bq : ((z == 1) ? bk : bv);
    float* C = (z == 0) ? g_Q : ((z == 1) ? g_K : g_V);
    gemm_body(x, W, b, C, z < 2, blockIdx.x, blockIdx.y);
}

__global__ __launch_bounds__(256) void proj_kernel(const float* __restrict__ Wo,
                                                   const float* __restrict__ bo,
                                                   float* __restrict__ out)
{
    gemm_body(g_O, Wo, bo, out, false, blockIdx.x, blockIdx.y);
}

// ---------------- per-(h,j) sum of K over d (for the |x| rewrite) ----------------
__global__ void sumk_kernel()
{
    int idx = blockIdx.x * blockDim.x + threadIdx.x;   // NH*S_LEN = 8192
    if (idx >= NH * S_LEN) return;
    int h = idx / S_LEN;
    int s = idx % S_LEN;
    const float* p = &g_K[s * DM + h * DU];
    float t = 0.f;
#pragma unroll
    for (int d = 0; d < DU; d++) t += p[d];
    g_sumK[h * S_LEN + s] = t;
}

// ---------------- attention tile kernel ----------------
// grid (it=16, jt=16, h=8); causal: only jt <= it does work.
// score path: p_ij = exp( TEMPC * (sumK_j - sum_d |Q_id - K_jd|) )
// (row-constant factors of the softmax dropped; they cancel in num/den.)
__global__ __launch_bounds__(256) void attn_kernel()
{
    const int it = blockIdx.x, jt = blockIdx.y, h = blockIdx.z;
    if (jt > it) return;

    __shared__ float Ks[64][32];
    __shared__ float Vs[64][32];
    __shared__ float sK[64];
    __shared__ float red[4][64][33];   // padded to kill bank conflicts
    __shared__ float redden[4][64];

    const int tid = threadIdx.x;
    const int ti = tid & 63;           // query row within tile
    const int tg = tid >> 6;           // 0..3, 4-way split over j

    // load K/V tiles (each thread: 2 float4 per tensor)
#pragma unroll
    for (int l = 0; l < 2; l++) {
        int f = tid + l * 256;
        int r = f >> 3;
        int c4 = (f & 7) << 2;
        *(float4*)&Ks[r][c4] = *(const float4*)&g_K[(jt * 64 + r) * DM + h * DU + c4];
        *(float4*)&Vs[r][c4] = *(const float4*)&g_V[(jt * 64 + r) * DM + h * DU + c4];
    }
    if (tid < 64) sK[tid] = g_sumK[h * S_LEN + jt * 64 + tid];

    // Q row into registers
    const int ig = it * 64 + ti;
    float q[32];
#pragma unroll
    for (int c4 = 0; c4 < 32; c4 += 4) {
        float4 v = *(const float4*)&g_Q[ig * DM + h * DU + c4];
        q[c4] = v.x; q[c4 + 1] = v.y; q[c4 + 2] = v.z; q[c4 + 3] = v.w;
    }
    __syncthreads();

    float acc[32];
#pragma unroll
    for (int d = 0; d < 32; d++) acc[d] = 0.f;
    float den = 0.f;

#pragma unroll 4
    for (int jj = 0; jj < 16; jj++) {
        int jl = (jj << 2) + tg;
        int jg = jt * 64 + jl;
        if (jg > ig) continue;         // causal
        float d0 = 0.f, d1 = 0.f;
#pragma unroll
        for (int d = 0; d < 32; d += 2) {
            d0 += fabsf(q[d]     - Ks[jl][d]);       // FADD + FADD|src|
            d1 += fabsf(q[d + 1] - Ks[jl][d + 1]);
        }
        float p = __expf(TEMPC * (sK[jl] - d0 - d1));
        den += p;
#pragma unroll
        for (int d = 0; d < 32; d++) acc[d] += p * Vs[jl][d];
    }

    // 4-way reduce across the tg split
#pragma unroll
    for (int d = 0; d < 32; d++) red[tg][ti][d] = acc[d];
    redden[tg][ti] = den;
    __syncthreads();

    const int i2 = tid >> 2;       // 0..63
    const int dg = tid & 3;        // handles 8 d's
    const int base = dg * 8;
    const int gi = it * 64 + i2;
    float outv[8];
#pragma unroll
    for (int dd = 0; dd < 8; dd++)
        outv[dd] = red[0][i2][base + dd] + red[1][i2][base + dd] +
                   red[2][i2][base + dd] + red[3][i2][base + dd];

    float* np = &g_pnum[(((size_t)jt * NH + h) * S_LEN + gi) * DU + base];
    float4 o0; o0.x = outv[0]; o0.y = outv[1]; o0.z = outv[2]; o0.w = outv[3];
    float4 o1; o1.x = outv[4]; o1.y = outv[5]; o1.z = outv[6]; o1.w = outv[7];
    *(float4*)&np[0] = o0;
    *(float4*)&np[4] = o1;
    if (dg == 0)
        g_pden[((size_t)jt * NH + h) * S_LEN + gi] =
            redden[0][i2] + redden[1][i2] + redden[2][i2] + redden[3][i2];
}

// ---------------- combine partials, divide, write O[s, h*32+d] ----------------
__global__ void reduce_kernel()
{
    int idx = blockIdx.x * 256 + threadIdx.x;  // S_LEN*DM = 262144
    int i = idx >> 8;          // sequence index
    int col = idx & 255;       // h*32 + d
    int h = col >> 5;
    int d = col & 31;
    int it = i >> 6;
    float num = 0.f, den = 0.f;
    for (int jt = 0; jt <= it; jt++) {
        num += g_pnum[(((size_t)jt * NH + h) * S_LEN + i) * DU + d];
        den += g_pden[((size_t)jt * NH + h) * S_LEN + i];
    }
    g_O[i * DM + col] = num / den;
}

// ---------------- launch ----------------
extern "C" void kernel_launch(void* const* d_in, const int* in_sizes, int n_in,
                              void* d_out, int out_size)
{
    const float* x  = (const float*)d_in[0];
    const float* Wq = (const float*)d_in[1];
    const float* bq = (const float*)d_in[2];
    const float* Wk = (const float*)d_in[3];
    const float* bk = (const float*)d_in[4];
    const float* Wv = (const float*)d_in[5];
    const float* bv = (const float*)d_in[6];
    const float* Wo = (const float*)d_in[7];
    const float* bo = (const float*)d_in[8];
    float* out = (float*)d_out;

    qkv_kernel<<<dim3(16, 4, 3), 256>>>(x, Wq, bq, Wk, bk, Wv, bv);
    sumk_kernel<<<32, 256>>>();
    attn_kernel<<<dim3(16, 16, 8), 256>>>();
    reduce_kernel<<<1024, 256>>>();
    proj_kernel<<<dim3(16, 4, 1), 256>>>(Wo, bo, out);
}

// round 3
// speedup vs baseline: 1.0504x; 1.0504x over previous
#include <cuda_runtime.h>
#include <cstdint>

#define S_LEN 1024
#define DM 256
#define NH 8
#define DU 32
#define NT 16               // S_LEN / 64
#define TEMPC 0.078125f     // TEMP / (2*DU) = 5/64

// ---------------- scratch (no allocations allowed) ----------------
__device__ float g_Q[S_LEN * DM];
__device__ float g_K[S_LEN * DM];
__device__ float g_V[S_LEN * DM];
__device__ float g_O[S_LEN * DM];
__device__ float g_sumK[NH * S_LEN];
__device__ float g_pnum[NT * NH * S_LEN * DU];   // [jt][h][i][d]
__device__ float g_pden[NT * NH * S_LEN];        // [jt][h][i]

// ---------------- packed f32x2 helpers (FADD2 / FFMA2) ----------------
__device__ __forceinline__ uint64_t f32x2_add(uint64_t a, uint64_t b) {
    uint64_t d; asm("add.rn.f32x2 %0, %1, %2;" : "=l"(d) : "l"(a), "l"(b)); return d;
}
__device__ __forceinline__ uint64_t f32x2_fma(uint64_t a, uint64_t b, uint64_t c) {
    uint64_t d; asm("fma.rn.f32x2 %0, %1, %2, %3;" : "=l"(d) : "l"(a), "l"(b), "l"(c)); return d;
}
__device__ __forceinline__ uint64_t f32x2_pack(float x, float y) {
    uint64_t d; asm("mov.b64 %0, {%1, %2};" : "=l"(d) : "f"(x), "f"(y)); return d;
}
__device__ __forceinline__ float2 f32x2_unpack(uint64_t a) {
    float2 r; asm("mov.b64 {%0, %1}, %2;" : "=f"(r.x), "=f"(r.y) : "l"(a)); return r;
}

// ---------------- 32x64-tile fp32 GEMM body (FFMA2) ----------------
// C[row, col] = act( A[S_LEN, DM] @ W[DM, DM] + b ); 2m x 4n per thread.
__device__ __forceinline__ void gemm_body(const float* __restrict__ A,
                                          const float* __restrict__ W,
                                          const float* __restrict__ b,
                                          float* __restrict__ C,
                                          bool sig, int bm, int bn)
{
    __shared__ float Ast[32][34];   // [k][m], +2 pad keeps 8B align & low conflicts
    __shared__ float Ws[32][64];    // [k][n]

    const int tid = threadIdx.x;
    const int tx = tid & 15;        // 4 output cols
    const int ty = tid >> 4;        // rows m = 2*ty, 2*ty+1

    uint64_t c2[4] = {0, 0, 0, 0};  // pairs over (m0,m1), for n = tx*4 + 0..3

    for (int k0 = 0; k0 < DM; k0 += 32) {
        {   // A tile: 32 rows x 32 k, transposed into smem
            int m = tid >> 3;               // 0..31
            int kc = (tid & 7) << 2;
            float4 v = *(const float4*)&A[(bm * 32 + m) * DM + k0 + kc];
            Ast[kc + 0][m] = v.x;
            Ast[kc + 1][m] = v.y;
            Ast[kc + 2][m] = v.z;
            Ast[kc + 3][m] = v.w;
        }
#pragma unroll
        for (int l = 0; l < 2; l++) {   // W tile 32 x 64
            int f = tid + l * 256;
            int k = f >> 4;
            int nc = (f & 15) << 2;
            *(float4*)&Ws[k][nc] = *(const float4*)&W[(k0 + k) * DM + bn * 64 + nc];
        }
        __syncthreads();
#pragma unroll
        for (int k = 0; k < 32; k++) {
            uint64_t am = *(const uint64_t*)&Ast[k][ty * 2];  // LDS.64, broadcast
            float4 bv = *(const float4*)&Ws[k][tx * 4];
            c2[0] = f32x2_fma(am, f32x2_pack(bv.x, bv.x), c2[0]);
            c2[1] = f32x2_fma(am, f32x2_pack(bv.y, bv.y), c2[1]);
            c2[2] = f32x2_fma(am, f32x2_pack(bv.z, bv.z), c2[2]);
            c2[3] = f32x2_fma(am, f32x2_pack(bv.w, bv.w), c2[3]);
        }
        __syncthreads();
    }

#pragma unroll
    for (int n = 0; n < 4; n++) {
        float2 cm = f32x2_unpack(c2[n]);
        float bb = b[bn * 64 + tx * 4 + n];
        float t0 = cm.x + bb, t1 = cm.y + bb;
        if (sig) { t0 = 1.0f / (1.0f + __expf(-t0)); t1 = 1.0f / (1.0f + __expf(-t1)); }
        C[(bm * 32 + ty * 2 + 0) * DM + bn * 64 + tx * 4 + n] = t0;
        C[(bm * 32 + ty * 2 + 1) * DM + bn * 64 + tx * 4 + n] = t1;
    }
}

__global__ __launch_bounds__(256) void qkv_kernel(const float* __restrict__ x,
                                                  const float* __restrict__ Wq, const float* __restrict__ bq,
                                                  const float* __restrict__ Wk, const float* __restrict__ bk,
                                                  const float* __restrict__ Wv, const float* __restrict__ bv)
{
    int z = blockIdx.z;
    const float* W = (z == 0) ? Wq : ((z == 1) ? Wk : Wv);
    const float* b = (z == 0) ? bq : ((z == 1) ? bk : bv);
    float* C = (z == 0) ? g_Q : ((z == 1) ? g_K : g_V);
    gemm_body(x, W, b, C, z < 2, blockIdx.x, blockIdx.y);
}

__global__ __launch_bounds__(256) void proj_kernel(const float* __restrict__ Wo,
                                                   const float* __restrict__ bo,
                                                   float* __restrict__ out)
{
    gemm_body(g_O, Wo, bo, out, false, blockIdx.x, blockIdx.y);
}

// ---------------- per-(h,j) sum of K over d ----------------
__global__ void sumk_kernel()
{
    int idx = blockIdx.x * blockDim.x + threadIdx.x;   // NH*S_LEN = 8192
    if (idx >= NH * S_LEN) return;
    int h = idx >> 10;
    int s = idx & 1023;
    const float4* p = (const float4*)&g_K[s * DM + h * DU];
    float t = 0.f;
#pragma unroll
    for (int c = 0; c < 8; c++) {
        float4 v = p[c];
        t += (v.x + v.y) + (v.z + v.w);
    }
    g_sumK[h * S_LEN + s] = t;
}

// ---------------- attention tile kernel (packed f32x2) ----------------
// p_ij = exp( TEMPC * (sumK_j - sum_d |Q_id - K_jd|) ); row-const terms cancel.
__global__ __launch_bounds__(256) void attn_kernel()
{
    const int it = blockIdx.x, jt = blockIdx.y, h = blockIdx.z;
    if (jt > it) return;

    __shared__ __align__(16) union SM {
        struct { float Kn[64][32]; float Vs[64][32]; float sK[64]; } a;
        struct { float red[4][64][33]; float redden[4][64]; } b;
    } sm;

    const int tid = threadIdx.x;
    const int ti = tid & 63;           // query row within tile
    const int tg = tid >> 6;           // 0..3, 4-way split over j

    // load K (negated) and V tiles
#pragma unroll
    for (int l = 0; l < 2; l++) {
        int f = tid + l * 256;
        int r = f >> 3;
        int c4 = (f & 7) << 2;
        float4 kv = *(const float4*)&g_K[(jt * 64 + r) * DM + h * DU + c4];
        kv.x = -kv.x; kv.y = -kv.y; kv.z = -kv.z; kv.w = -kv.w;
        *(float4*)&sm.a.Kn[r][c4] = kv;
        *(float4*)&sm.a.Vs[r][c4] = *(const float4*)&g_V[(jt * 64 + r) * DM + h * DU + c4];
    }
    if (tid < 64) sm.a.sK[tid] = g_sumK[h * S_LEN + jt * 64 + tid];

    const int ig = it * 64 + ti;
    uint64_t qp[16];
    {
        const ulonglong2* qg = (const ulonglong2*)&g_Q[ig * DM + h * DU];
#pragma unroll
        for (int c = 0; c < 8; c++) { ulonglong2 t = qg[c]; qp[2 * c] = t.x; qp[2 * c + 1] = t.y; }
    }
    __syncthreads();

    uint64_t acc[16];
#pragma unroll
    for (int c = 0; c < 16; c++) acc[c] = 0;
    float den = 0.f;
    const uint64_t AMASK = 0x7FFFFFFF7FFFFFFFULL;

#pragma unroll 2
    for (int jj = 0; jj < 16; jj++) {
        int jl = (jj << 2) + tg;
        if (jt * 64 + jl > ig) continue;     // causal
        const ulonglong2* kr = (const ulonglong2*)&sm.a.Kn[jl][0];
        uint64_t s0 = 0, s1 = 0;
#pragma unroll
        for (int c = 0; c < 8; c++) {
            ulonglong2 kc = kr[c];
            uint64_t t0 = f32x2_add(qp[2 * c], kc.x) & AMASK;       // FADD2 + 2xLOP3
            uint64_t t1 = f32x2_add(qp[2 * c + 1], kc.y) & AMASK;
            s0 = f32x2_add(s0, t0);
            s1 = f32x2_add(s1, t1);
        }
        float2 u0 = f32x2_unpack(s0), u1 = f32x2_unpack(s1);
        float s = (u0.x + u0.y) + (u1.x + u1.y);
        float p = __expf(TEMPC * (sm.a.sK[jl] - s));
        den += p;
        uint64_t pp = f32x2_pack(p, p);
        const ulonglong2* vr = (const ulonglong2*)&sm.a.Vs[jl][0];
#pragma unroll
        for (int c = 0; c < 8; c++) {
            ulonglong2 vc = vr[c];
            acc[2 * c]     = f32x2_fma(pp, vc.x, acc[2 * c]);       // FFMA2
            acc[2 * c + 1] = f32x2_fma(pp, vc.y, acc[2 * c + 1]);
        }
    }

    __syncthreads();   // all warps done with Kn/Vs before overlay write
#pragma unroll
    for (int c = 0; c < 16; c++) {
        float2 u = f32x2_unpack(acc[c]);
        sm.b.red[tg][ti][2 * c]     = u.x;
        sm.b.red[tg][ti][2 * c + 1] = u.y;
    }
    sm.b.redden[tg][ti] = den;
    __syncthreads();

    const int i2 = tid >> 2;       // 0..63
    const int dg = tid & 3;        // 8 d's each
    const int base = dg * 8;
    const int gi = it * 64 + i2;
    float outv[8];
#pragma unroll
    for (int dd = 0; dd < 8; dd++)
        outv[dd] = (sm.b.red[0][i2][base + dd] + sm.b.red[1][i2][base + dd]) +
                   (sm.b.red[2][i2][base + dd] + sm.b.red[3][i2][base + dd]);

    float* np = &g_pnum[(((size_t)jt * NH + h) * S_LEN + gi) * DU + base];
    *(float4*)&np[0] = make_float4(outv[0], outv[1], outv[2], outv[3]);
    *(float4*)&np[4] = make_float4(outv[4], outv[5], outv[6], outv[7]);
    if (dg == 0)
        g_pden[((size_t)jt * NH + h) * S_LEN + gi] =
            (sm.b.redden[0][i2] + sm.b.redden[1][i2]) +
            (sm.b.redden[2][i2] + sm.b.redden[3][i2]);
}

// ---------------- combine partials, divide, write O[s, h*32+d] ----------------
__global__ __launch_bounds__(256) void reduce_kernel()
{
    int idx = blockIdx.x * 256 + threadIdx.x;  // 65536 threads, float4 each
    int i = idx >> 6;          // sequence index
    int r = idx & 63;
    int h = r >> 3;
    int d4 = (r & 7) << 2;
    int it = i >> 6;
    const float* pn = &g_pnum[((size_t)h * S_LEN + i) * DU + d4];
    const float* pd = &g_pden[(size_t)h * S_LEN + i];
    const size_t sj = (size_t)NH * S_LEN * DU;
    const size_t sd = (size_t)NH * S_LEN;
    float4 n = make_float4(0.f, 0.f, 0.f, 0.f);
    float den = 0.f;
#pragma unroll 4
    for (int jjt = 0; jjt <= it; jjt++) {
        float4 v = *(const float4*)(pn + (size_t)jjt * sj);
        den += pd[(size_t)jjt * sd];
        n.x += v.x; n.y += v.y; n.z += v.z; n.w += v.w;
    }
    float inv = 1.0f / den;
    *(float4*)&g_O[i * DM + h * DU + d4] =
        make_float4(n.x * inv, n.y * inv, n.z * inv, n.w * inv);
}

// ---------------- launch ----------------
extern "C" void kernel_launch(void* const* d_in, const int* in_sizes, int n_in,
                              void* d_out, int out_size)
{
    const float* x  = (const float*)d_in[0];
    const float* Wq = (const float*)d_in[1];
    const float* bq = (const float*)d_in[2];
    const float* Wk = (const float*)d_in[3];
    const float* bk = (const float*)d_in[4];
    const float* Wv = (const float*)d_in[5];
    const float* bv = (const float*)d_in[6];
    const float* Wo = (const float*)d_in[7];
    const float* bo = (const float*)d_in[8];
    float* out = (float*)d_out;

    qkv_kernel<<<dim3(32, 4, 3), 256>>>(x, Wq, bq, Wk, bk, Wv, bv);
    sumk_kernel<<<32, 256>>>();
    attn_kernel<<<dim3(16, 16, 8), 256>>>();
    reduce_kernel<<<256, 256>>>();
    proj_kernel<<<dim3(32, 4, 1), 256>>>(Wo, bo, out);
}